// round 9
// baseline (speedup 1.0000x reference)
#include <cuda_runtime.h>
#include <cuda_bf16.h>
#include <math.h>
#include <stdint.h>

// ----------------------------------------------------------------------------
// MemoryNetwork, GB300 sm_103a (PTX target sm_103 => family-portable ISA only)
//
//   M1[d,m,:] = W_topic  @ mems_d[d,m]; M2 likewise (rows 0..95 topic, 96..191 domain)
//   P[b,r]    = feature_b . M[r]   via mma.sync bf16 hi/lo split (3 passes, fp32 acc)
//   fused row-norm + topic softmax + domain softmax epilogue.
//
// R9: fused = 512 thr, M=128, double-buffered, mma-first chunk schedule (tensor
//     pipe primed before producer work). build_M = 1024 blocks, 96-e chains.
// ----------------------------------------------------------------------------

#define K_DIM   2048
#define EMB     768
#define TAUF    32.0f
#define NROWS   192
#define KC      64            // bf16 K per chunk
#define NCH     (K_DIM / KC)  // 32

__device__ __align__(16) unsigned short g_Bh[NROWS * K_DIM];
__device__ __align__(16) unsigned short g_Bl[NROWS * K_DIM];

// ---------------- helpers ----------------
__device__ __forceinline__ uint32_t smem_u32(const void* p) {
    uint32_t a;
    asm("{ .reg .u64 t; cvta.to.shared.u64 t, %1; cvt.u32.u64 %0, t; }" : "=r"(a) : "l"(p));
    return a;
}
__device__ __forceinline__ unsigned long long dup2(float x) {
    unsigned long long r; asm("mov.b64 %0, {%1, %1};" : "=l"(r) : "f"(x)); return r;
}
__device__ __forceinline__ void ffma2(unsigned long long& d, unsigned long long a,
                                      unsigned long long b) {
    asm("fma.rn.f32x2 %0, %1, %2, %0;" : "+l"(d) : "l"(a), "l"(b));
}
__device__ __forceinline__ float2 unpack2(unsigned long long v) {
    float2 f; asm("mov.b64 {%0, %1}, %2;" : "=f"(f.x), "=f"(f.y) : "l"(v)); return f;
}
__device__ __forceinline__ uint32_t cvt_bf16x2(float lo, float hi) {
    uint32_t r; asm("cvt.rn.bf16x2.f32 %0, %1, %2;" : "=r"(r) : "f"(hi), "f"(lo)); return r;
}
__device__ __forceinline__ void ldsm4(uint32_t* r, uint32_t addr) {
    asm volatile("ldmatrix.sync.aligned.m8n8.x4.shared.b16 {%0,%1,%2,%3}, [%4];"
                 : "=r"(r[0]), "=r"(r[1]), "=r"(r[2]), "=r"(r[3]) : "r"(addr));
}
__device__ __forceinline__ void mma16816(float* d, const uint32_t* a, const uint32_t* b) {
    asm volatile("mma.sync.aligned.m16n8k16.row.col.f32.bf16.bf16.f32 "
                 "{%0,%1,%2,%3}, {%4,%5,%6,%7}, {%8,%9}, {%0,%1,%2,%3};"
                 : "+f"(d[0]), "+f"(d[1]), "+f"(d[2]), "+f"(d[3])
                 : "r"(a[0]), "r"(a[1]), "r"(a[2]), "r"(a[3]), "r"(b[0]), "r"(b[1]));
}
#define CP16(dst, src)  asm volatile("cp.async.cg.shared.global [%0], [%1], 16;" \
                                     :: "r"(dst), "l"(src) : "memory")
#define CP_COMMIT()     asm volatile("cp.async.commit_group;" ::: "memory")
#define CP_WAIT0()      asm volatile("cp.async.wait_group 0;" ::: "memory")

// ----------------------------------------------------------------------------
// Kernel A: M[row][k] = sum_e mem[row][e] * W[e][k], bf16 hi/lo out
// grid (64 kchunk, 16 rowgroup) = 1024 blocks, 256 thr = 32 kcols x 8 egroups(96e)
// ----------------------------------------------------------------------------
__global__ void __launch_bounds__(256) build_M_kernel(
    const float* __restrict__ Wt, const float* __restrict__ Wd,
    const float* __restrict__ memtab, const void* __restrict__ catp)
{
    __shared__ __align__(16) float memsm[EMB][12];    // 36864 B; overlaid by partials
    float* part = &memsm[0][0];                       // [8][32][12] after compute

    const int tid = threadIdx.x;
    const int kx  = blockIdx.x;        // 0..63
    const int ry  = blockIdx.y;        // 0..15
    const int mtx = ry >> 3;
    const int grp = ry & 7;
    const int kl  = tid & 31;
    const int k   = kx * 32 + kl;
    const int eg  = tid >> 5;          // 0..7
    const int base_row = mtx * 96 + grp * 12;

    const int* c32 = (const int*)catp;
    bool is64 = true;
    #pragma unroll
    for (int j = 0; j < 9; j++) if (c32[2 * j + 1] != 0) is64 = false;
    int catv[9];
    #pragma unroll
    for (int j = 0; j < 9; j++)
        catv[j] = is64 ? (int)(((const long long*)catp)[j]) : c32[j];

    for (int idx = tid; idx < 12 * EMB; idx += 256) {
        int rr = idx / EMB, e = idx % EMB;
        int gr = grp * 12 + rr;
        float v = 0.0f;
        if (gr < 90) {
            int d = gr / 10, m = gr % 10;
            v = memtab[(catv[d] * 10 + m) * EMB + e];
        }
        memsm[e][rr] = v;
    }
    __syncthreads();

    const float* W = mtx ? Wd : Wt;
    unsigned long long acc[6];
    #pragma unroll
    for (int j = 0; j < 6; j++) acc[j] = 0ull;

    const int e0 = eg * 96;
    #pragma unroll 4
    for (int e = e0; e < e0 + 96; e++) {
        unsigned long long wd = dup2(W[(size_t)e * K_DIM + k]);
        const ulonglong2* mr = (const ulonglong2*)(&memsm[e][0]);
        ulonglong2 p0 = mr[0], p1 = mr[1], p2 = mr[2];
        ffma2(acc[0], p0.x, wd); ffma2(acc[1], p0.y, wd);
        ffma2(acc[2], p1.x, wd); ffma2(acc[3], p1.y, wd);
        ffma2(acc[4], p2.x, wd); ffma2(acc[5], p2.y, wd);
    }

    float vals[12];
    #pragma unroll
    for (int j = 0; j < 6; j++) {
        float2 v = unpack2(acc[j]);
        vals[2 * j] = v.x; vals[2 * j + 1] = v.y;
    }
    __syncthreads();                      // memsm reads complete
    float* pp = part + (eg * 32 + kl) * 12;
    #pragma unroll
    for (int j = 0; j < 12; j++) pp[j] = vals[j];
    __syncthreads();

    // reduce 8 partials, split bf16 hi/lo, store (384 outputs)
    for (int o = tid; o < 384; o += 256) {
        int okl = o & 31, row = o >> 5;
        float s = 0.0f;
        #pragma unroll
        for (int g = 0; g < 8; g++) s += part[(g * 32 + okl) * 12 + row];
        uint32_t u = __float_as_uint(s);
        float hif = __uint_as_float(u & 0xFFFF0000u);
        float lo  = s - hif;
        __nv_bfloat16 lb = __float2bfloat16(lo);
        size_t off = (size_t)(base_row + row) * K_DIM + kx * 32 + okl;
        g_Bh[off] = (unsigned short)(u >> 16);
        g_Bl[off] = *(unsigned short*)&lb;
    }
}

// ----------------------------------------------------------------------------
// Fused mma.sync GEMM + norms + softmaxes (double-buffered, mma-first schedule)
// grid 128 CTAs x 512 threads (16 warps as 4x4); per-CTA tile M=128, N=192
// Per buffer: Ah/Al 128x72 bf16 (18432 B), Bh/Bl 192x72 bf16 (27648 B) = 92160
// ----------------------------------------------------------------------------
#define BM       128
#define LDS_A    72
#define AH_OFF   0
#define AL_OFF   18432
#define BH_OFF   36864
#define BL_OFF   64512
#define BUF_STR  92160
#define CS_LD    194
#define RS_OFF   (2 * BUF_STR)               // 184320 (> Cs = 128*194*4 = 99328)
#define SMEM_TOT (RS_OFF + BM * 4)           // 184832

__global__ void __launch_bounds__(512, 1) fused_kernel(
    const float* __restrict__ feat, float* __restrict__ out)
{
    extern __shared__ __align__(16) char smem[];
    const uint32_t sbase = smem_u32(smem);
    float* Cs     = (float*)smem;
    float* rowsum = (float*)(smem + RS_OFF);

    const int tid  = threadIdx.x;
    const int lane = tid & 31;
    const int wid  = tid >> 5;
    const int wr   = wid >> 2;      // 0..3 -> 32-row band
    const int wc   = wid & 3;       // 0..3 -> 48-col band
    const int b0   = blockIdx.x * BM;

    if (tid < BM) rowsum[tid] = 0.0f;

    float acc[2][6][4];
    #pragma unroll
    for (int i = 0; i < 2; i++)
        #pragma unroll
        for (int j = 0; j < 6; j++)
            #pragma unroll
            for (int q = 0; q < 4; q++) acc[i][j][q] = 0.0f;

    float ss[2] = {0.f, 0.f};
    float4 aregs[4];

    auto ldgA = [&](int kc) {
        #pragma unroll
        for (int l = 0; l < 2; l++) {
            int ci = tid + 512 * l, r = ci >> 3, cc = ci & 7;
            const float4* src = (const float4*)(feat + (size_t)(b0 + r) * K_DIM + kc + cc * 8);
            aregs[2 * l]     = src[0];
            aregs[2 * l + 1] = src[1];
        }
    };
    auto stsA = [&](uint32_t bufo) {
        #pragma unroll
        for (int l = 0; l < 2; l++) {
            int ci = tid + 512 * l, r = ci >> 3, cc = ci & 7;
            float4 v0 = aregs[2 * l], v1 = aregs[2 * l + 1];
            float f[8] = {v0.x, v0.y, v0.z, v0.w, v1.x, v1.y, v1.z, v1.w};
            ss[l] += f[0]*f[0] + f[1]*f[1] + f[2]*f[2] + f[3]*f[3]
                   + f[4]*f[4] + f[5]*f[5] + f[6]*f[6] + f[7]*f[7];
            uint32_t hi[4], lo[4];
            #pragma unroll
            for (int p = 0; p < 4; p++) {
                uint32_t u0 = __float_as_uint(f[2*p]), u1 = __float_as_uint(f[2*p+1]);
                hi[p] = (u0 >> 16) | (u1 & 0xFFFF0000u);
                float l0 = f[2*p]   - __uint_as_float(u0 & 0xFFFF0000u);
                float l1 = f[2*p+1] - __uint_as_float(u1 & 0xFFFF0000u);
                lo[p] = cvt_bf16x2(l0, l1);
            }
            uint32_t boff = bufo + (uint32_t)(r * (LDS_A * 2) + cc * 16);
            *(uint4*)(smem + AH_OFF + boff) = make_uint4(hi[0], hi[1], hi[2], hi[3]);
            *(uint4*)(smem + AL_OFF + boff) = make_uint4(lo[0], lo[1], lo[2], lo[3]);
        }
    };
    auto cpB = [&](int kc, uint32_t bufo) {
        #pragma unroll
        for (int l = 0; l < 3; l++) {
            int ci = tid + 512 * l, r = ci >> 3, cc = ci & 7;
            size_t g = (size_t)r * K_DIM + kc + cc * 8;
            uint32_t d = sbase + bufo + (uint32_t)(r * (LDS_A * 2) + cc * 16);
            CP16(d + BH_OFF, g_Bh + g);
            CP16(d + BL_OFF, g_Bl + g);
        }
    };

    const int mbase = wr * 32;
    const int nbase = wc * 48;

    auto doK16 = [&](int k16, uint32_t rbuf) {
        const uint32_t akoff = (uint32_t)(k16 * 16 + (lane >> 4) * 8) * 2;
        const uint32_t bkoff = (uint32_t)(k16 * 16 + ((lane >> 3) & 1) * 8) * 2;

        uint32_t ah[2][4], al[2][4];
        #pragma unroll
        for (int mt = 0; mt < 2; mt++) {
            uint32_t rowb = (uint32_t)(mbase + mt * 16 + (lane & 15)) * (LDS_A * 2);
            ldsm4(ah[mt], sbase + rbuf + AH_OFF + rowb + akoff);
            ldsm4(al[mt], sbase + rbuf + AL_OFF + rowb + akoff);
        }
        uint32_t bh[3][4];
        #pragma unroll
        for (int bt = 0; bt < 3; bt++) {
            uint32_t rowb = (uint32_t)(nbase + bt * 16 + (lane & 7) + ((lane >> 4) << 3))
                          * (LDS_A * 2);
            ldsm4(bh[bt], sbase + rbuf + BH_OFF + rowb + bkoff);
        }
        #pragma unroll
        for (int mt = 0; mt < 2; mt++)
            #pragma unroll
            for (int nt = 0; nt < 6; nt++) {
                mma16816(acc[mt][nt], ah[mt], &bh[nt >> 1][(nt & 1) * 2]);
                mma16816(acc[mt][nt], al[mt], &bh[nt >> 1][(nt & 1) * 2]);
            }
        uint32_t bl[3][4];
        #pragma unroll
        for (int bt = 0; bt < 3; bt++) {
            uint32_t rowb = (uint32_t)(nbase + bt * 16 + (lane & 7) + ((lane >> 4) << 3))
                          * (LDS_A * 2);
            ldsm4(bl[bt], sbase + rbuf + BL_OFF + rowb + bkoff);
        }
        #pragma unroll
        for (int mt = 0; mt < 2; mt++)
            #pragma unroll
            for (int nt = 0; nt < 6; nt++)
                mma16816(acc[mt][nt], ah[mt], &bl[nt >> 1][(nt & 1) * 2]);
    };

    // ---- prologue: chunk 0 into buf0; prefetch chunk 1's A into regs ----
    ldgA(0);
    cpB(0, 0);
    CP_COMMIT();
    stsA(0);           // consumes chunk 0 from aregs
    ldgA(KC);          // aregs <- chunk 1 (chunk 0 already stored)
    CP_WAIT0();
    __syncthreads();

    for (int c = 0; c < NCH; c++) {
        const uint32_t rbuf = (uint32_t)(c & 1) * BUF_STR;
        const uint32_t wbuf = rbuf ^ BUF_STR;

        // prime the tensor pipe before producer work
        doK16(0, rbuf);

        if (c + 1 < NCH) {
            cpB((c + 1) * KC, wbuf);              // async B for next chunk
            CP_COMMIT();
            stsA(wbuf);                           // consume aregs (chunk c+1) FIRST
            if (c + 2 < NCH) ldgA((c + 2) * KC);  // THEN refill; hides under mma
        }

        doK16(1, rbuf);
        doK16(2, rbuf);
        doK16(3, rbuf);

        CP_WAIT0();
        __syncthreads();
    }

    // ---- C fragments -> smem (buffers reused) ----
    #pragma unroll
    for (int mt = 0; mt < 2; mt++)
        #pragma unroll
        for (int nt = 0; nt < 6; nt++) {
            int row = wr * 32 + mt * 16 + (lane >> 2);
            int col = wc * 48 + nt * 8 + (lane & 3) * 2;
            *(float2*)&Cs[row * CS_LD + col]       = make_float2(acc[mt][nt][0], acc[mt][nt][1]);
            *(float2*)&Cs[(row + 8) * CS_LD + col] = make_float2(acc[mt][nt][2], acc[mt][nt][3]);
        }
    #pragma unroll
    for (int l = 0; l < 2; l++)
        atomicAdd(&rowsum[(tid >> 3) + 64 * l], ss[l]);
    __syncthreads();

    // ---- per-row softmax chain ----
    if (tid < BM) {
        const int    b  = b0 + tid;
        const float  s  = TAUF / fmaxf(sqrtf(rowsum[tid]), 1e-12f);
        const float* cr = Cs + tid * CS_LD;

        float L[9];
        #pragma unroll
        for (int d = 0; d < 9; d++) {
            float mx = -1e30f;
            #pragma unroll
            for (int m = 0; m < 10; m++) mx = fmaxf(mx, cr[d * 10 + m]);
            float se = 0.f, ac = 0.f;
            #pragma unroll
            for (int m = 0; m < 10; m++) {
                float e = expf(s * (cr[d * 10 + m] - mx));
                se += e;
                ac += e * cr[96 + d * 10 + m];
            }
            L[d] = s * ac / se;
        }
        float mx2 = -1e30f;
        #pragma unroll
        for (int d = 0; d < 9; d++) mx2 = fmaxf(mx2, L[d]);
        float ex[9], s2 = 0.f;
        #pragma unroll
        for (int d = 0; d < 9; d++) { ex[d] = expf(L[d] - mx2); s2 += ex[d]; }
        const float inv = 1.0f / s2;
        #pragma unroll
        for (int d = 0; d < 9; d++) out[b * 9 + d] = ex[d] * inv;
    }
}

// ----------------------------------------------------------------------------
extern "C" void kernel_launch(void* const* d_in, const int* in_sizes, int n_in,
                              void* d_out, int out_size)
{
    const float* feature = (const float*)d_in[0];  // (16384, 2048)
    const float* Wt      = (const float*)d_in[1];  // (768, 2048)
    const float* Wd      = (const float*)d_in[2];  // (768, 2048)
    const float* memtab  = (const float*)d_in[3];  // (9, 10, 768)
    const void*  cat     = d_in[4];                // (16384,) int32/int64

    cudaFuncSetAttribute(fused_kernel,
                         cudaFuncAttributeMaxDynamicSharedMemorySize, SMEM_TOT);

    dim3 gA(64, 16);
    build_M_kernel<<<gA, 256>>>(Wt, Wd, memtab, cat);
    fused_kernel<<<16384 / BM, 512, SMEM_TOT>>>(feature, (float*)d_out);
}